// round 14
// baseline (speedup 1.0000x reference)
#include <cuda_runtime.h>
#include <math.h>

#define NB 16
#define NN 2048
#define NK 20
#define NC 64

typedef unsigned long long u64;

// ---- scratch (static __device__, allocation-free) ----
__device__ int   g_idxT[NB*NK*NN];          // knn indices, [b][k][n]
__device__ float g_bxT [NB*NN*NC];          // act_g * (basis_W @ x), point-major [p][c]
__device__ float g_cst [NB*NN*NC];          // edge_g*((We2-We1)@x) + edge_be, [p][o]
__device__ float g_glT [NB*NK*32*NN];       // glf transposed to [b][k][c][n]

// ---- packed f32x2 helpers (Blackwell FFMA2) ----
__device__ __forceinline__ u64 f2pack(float lo, float hi) {
    u64 r; asm("mov.b64 %0, {%1, %2};" : "=l"(r) : "f"(lo), "f"(hi)); return r;
}
__device__ __forceinline__ void f2unpack(u64 v, float& lo, float& hi) {
    asm("mov.b64 {%0, %1}, %2;" : "=f"(lo), "=f"(hi) : "l"(v));
}
__device__ __forceinline__ void ffma2(u64& d, u64 a, u64 b) {
    asm("fma.rn.f32x2 %0, %1, %2, %3;" : "=l"(d) : "l"(a), "l"(b), "l"(d));
}

#define LEAKY(v) ((v) > 0.f ? (v) : 0.2f*(v))
#define IDX_SENT 0x7FFFFFFF

// exact warp insert into distributed (v desc, idx asc) top-20 list.
// comparator-correct for ANY processing order (lexicographic ties).
__device__ __forceinline__ void warp_insert_exact(
    float& v, int& idx, float pdv, int pdi, int lane)
{
    unsigned cmp = __ballot_sync(0xFFFFFFFFu,
        (pdv > v) || (pdv == v && pdi < idx)) & 0xFFFFFu;
    if (cmp) {
        int pos = __ffs((int)cmp) - 1;
        float nv = __shfl_up_sync(0xFFFFFFFFu, v, 1);
        int  nid = __shfl_up_sync(0xFFFFFFFFu, idx, 1);
        if (lane > pos)  { v = nv;  idx = nid; }
        if (lane == pos) { v = pdv; idx = pdi; }
    }
}

// =====================================================================
// KNN, two-phase:
//   Phase 1 (ALU only): each lane keeps sorted top-4 of its 64 strided
//     candidates (m = j*32 + lane; ascending idx per lane -> strict >
//     ripple is tie-stable). dmax tracks best discarded value.
//   Phase 2 (small MIO): merge 128 survivors via exact-comparator warp
//     inserts (order-independent, matches lax.top_k ties exactly).
//   Guard: if any lane discarded a value >= final 20th (lane held >=5 of
//     top-20; ~1% of queries), re-run a full exact streaming pass.
// Self excluded (reference drops top-1 == self, pd = 0 bit-exact).
// =====================================================================
__global__ void __launch_bounds__(256)
knn_kernel(const float* __restrict__ pos)
{
    __shared__ float4 sp[NN];
    const int b    = blockIdx.y;
    const int tid  = threadIdx.x;
    const int w    = tid >> 5;
    const int lane = tid & 31;
    const float* pb = pos + (size_t)b*3*NN;
    for (int m = tid; m < NN; m += 256) {
        float xx = pb[m], yy = pb[NN + m], zz = pb[2*NN + m];
        sp[m] = make_float4(xx, yy, zz, xx*xx + yy*yy + zz*zz);
    }
    __syncthreads();

    const int qbase = blockIdx.x*32 + w*4;
    #pragma unroll 1
    for (int qi = 0; qi < 4; qi++) {
        const int q = qbase + qi;
        const float4 pq = sp[q];

        // ---- phase 1: per-lane sorted top-4 (branchless, no MIO) ----
        float lv0 = -INFINITY, lv1 = -INFINITY, lv2 = -INFINITY, lv3 = -INFINITY;
        int   li0 = IDX_SENT,  li1 = IDX_SENT,  li2 = IDX_SENT,  li3 = IDX_SENT;
        float dmax = -INFINITY;

        #pragma unroll 1
        for (int j = 0; j < 64; j++) {
            const int m = j*32 + lane;
            float4 pm = sp[m];
            float pd = 2.0f*(pq.x*pm.x + pq.y*pm.y + pq.z*pm.z) - pq.w - pm.w;
            pd = (m == q) ? -INFINITY : pd;
            bool c3 = pd > lv3;
            bool c2 = pd > lv2;
            bool c1 = pd > lv1;
            bool c0 = pd > lv0;
            dmax = fmaxf(dmax, c3 ? lv3 : pd);
            lv3 = c2 ? lv2 : (c3 ? pd : lv3);  li3 = c2 ? li2 : (c3 ? m : li3);
            lv2 = c1 ? lv1 : (c2 ? pd : lv2);  li2 = c1 ? li1 : (c2 ? m : li2);
            lv1 = c0 ? lv0 : (c1 ? pd : lv1);  li1 = c0 ? li0 : (c1 ? m : li1);
            lv0 = c0 ? pd : lv0;               li0 = c0 ? m  : li0;
        }

        // ---- phase 2: exact merge of 128 survivors ----
        float v = -INFINITY;
        int   idx = IDX_SENT;
        #pragma unroll 1
        for (int r = 0; r < 4; r++) {
            float pv = (r==0) ? lv0 : (r==1) ? lv1 : (r==2) ? lv2 : lv3;
            int   pi = (r==0) ? li0 : (r==1) ? li1 : (r==2) ? li2 : li3;
            float tv = __shfl_sync(0xFFFFFFFFu, v, 19);
            int   ti = __shfl_sync(0xFFFFFFFFu, idx, 19);
            unsigned mask = __ballot_sync(0xFFFFFFFFu,
                (pv > tv) || (pv == tv && pi < ti));
            while (mask) {
                int src = __ffs((int)mask) - 1;
                float pdv = __shfl_sync(0xFFFFFFFFu, pv, src);
                int   pdi = __shfl_sync(0xFFFFFFFFu, pi, src);
                mask &= mask - 1;
                warp_insert_exact(v, idx, pdv, pdi, lane);
            }
        }

        // ---- overflow guard: lane may have discarded a top-20 member ----
        {
            float Tv = __shfl_sync(0xFFFFFFFFu, v, 19);
            unsigned slow = __ballot_sync(0xFFFFFFFFu, dmax >= Tv);
            if (slow) {
                // full exact streaming pass (rare, warp-uniform)
                v = -INFINITY; idx = IDX_SENT;
                #pragma unroll 1
                for (int blk = 0; blk < NN; blk += 32) {
                    const int m = blk + lane;
                    float4 pm = sp[m];
                    float pd = 2.0f*(pq.x*pm.x + pq.y*pm.y + pq.z*pm.z) - pq.w - pm.w;
                    float tv = __shfl_sync(0xFFFFFFFFu, v, 19);
                    int   ti = __shfl_sync(0xFFFFFFFFu, idx, 19);
                    unsigned mask = __ballot_sync(0xFFFFFFFFu,
                        ((pd > tv) || (pd == tv && m < ti)) && (m != q));
                    while (mask) {
                        int src = __ffs((int)mask) - 1;
                        float pdv = __shfl_sync(0xFFFFFFFFu, pd, src);
                        mask &= mask - 1;
                        warp_insert_exact(v, idx, pdv, blk + src, lane);
                    }
                }
            }
        }

        if (lane < NK)
            g_idxT[((size_t)b*NK + lane)*NN + q] = idx;
    }
}

// =====================================================================
// prep (unchanged)
// =====================================================================
__global__ void prep_kernel(const float* __restrict__ x,
                            const float* __restrict__ basis_W,
                            const float* __restrict__ edge_W,
                            const float* __restrict__ act_g,
                            const float* __restrict__ edge_g,
                            const float* __restrict__ edge_be)
{
    __shared__ float sB[64*64];
    __shared__ float sD[64*64];
    __shared__ float sag[64], seg[64], seb[64];
    const int tid = threadIdx.x;
    for (int i = tid; i < 4096; i += blockDim.x) {
        sB[i] = basis_W[i];
        int o = i >> 6, c = i & 63;
        sD[i] = edge_W[o*128 + 64 + c] - edge_W[o*128 + c];
    }
    for (int i = tid; i < 64; i += blockDim.x) {
        sag[i] = act_g[i]; seg[i] = edge_g[i]; seb[i] = edge_be[i];
    }
    __syncthreads();

    const int p = blockIdx.x * blockDim.x + tid;
    const int b = p / NN, n = p % NN;
    const float* xp = x + (size_t)b*64*NN + n;
    float xv[64];
    #pragma unroll
    for (int c = 0; c < 64; c++) xv[c] = xp[(size_t)c*NN];

    float* bo = g_bxT + (size_t)p*64;
    #pragma unroll 4
    for (int o = 0; o < 64; o++) {
        float acc = 0.f;
        #pragma unroll
        for (int c = 0; c < 64; c++) acc += sB[o*64+c]*xv[c];
        bo[o] = acc * sag[o];
    }
    float* co = g_cst + (size_t)p*64;
    #pragma unroll 4
    for (int o = 0; o < 64; o++) {
        float acc = 0.f;
        #pragma unroll
        for (int c = 0; c < 64; c++) acc += sD[o*64+c]*xv[c];
        co[o] = acc*seg[o] + seb[o];
    }
}

// =====================================================================
// glf transpose (unchanged)
// =====================================================================
__global__ void tr_kernel(const float* __restrict__ glf)
{
    __shared__ float s[64*21];
    const int n0 = blockIdx.x * 64;
    const int c  = blockIdx.y;
    const int b  = blockIdx.z;
    const int tid = threadIdx.x;
    const float* in = glf + (((size_t)b*32 + c)*NN + n0) * NK;
    #pragma unroll
    for (int u = 0; u < 5; u++) {
        int f = tid + u*256;
        int n = f / 20, k = f % 20;
        s[n*21 + k] = in[f];
    }
    __syncthreads();
    #pragma unroll
    for (int u = 0; u < 5; u++) {
        int f = tid + u*256;
        int k = f >> 6, n = f & 63;
        g_glT[(((size_t)b*NK + k)*32 + c)*NN + n0 + n] = s[n*21 + k];
    }
}

// =====================================================================
// main fused kernel (round-10 best: 337us): 256 thr, 128-pt tile,
// 4 pts/thread, dk2-into-ff1 fold, deferred STS, appf pipelining.
// =====================================================================
__global__ void __launch_bounds__(256, 2)
main_kernel(const float* __restrict__ appf,
            const float* __restrict__ dk_W1, const float* __restrict__ dk_b1,
            const float* __restrict__ dk_g1, const float* __restrict__ dk_be1,
            const float* __restrict__ dk_W2, const float* __restrict__ dk_b2,
            const float* __restrict__ act_b,
            const float* __restrict__ ff_W1, const float* __restrict__ ff_g1,
            const float* __restrict__ ff_be1, const float* __restrict__ ff_W2,
            const float* __restrict__ edge_W, const float* __restrict__ edge_g,
            float* __restrict__ out)
{
    extern __shared__ float sm[];
    float* wW1t = sm;             // [8][16]   128
    float* wb1  = wW1t + 128;     // 16
    float* wW2t = wb1  + 16;      // [16][32]  512
    float* wb2  = wW2t + 512;     // 32
    float* wAh  = wb2  + 32;      // [16][32]  512  folded (g*W1a)@W2, [c][o]
    float* wbf  = wAh  + 512;     // 32
    float* wBg  = wbf  + 32;      // [32][32]  1024 g*W1[:,32:], [c][o]
    float* wF2t = wBg  + 1024;    // [32][64]  2048
    float* wab  = wF2t + 2048;    // 64
    float* wWEt = wab  + 64;      // [64][64]  4096
    float* t_in = wWEt + 4096;    // [8][128]  1024
    float* t_h  = t_in + 1024;    // [16][128] 2048
    float* t_rif= t_h  + 2048;    // [64][128] 8192
    float* t_att= t_rif+ 8192;    // [32][128] 4096
    int*   s_idx= (int*)(t_att + 4096);   // 128

    const int tid = threadIdx.x;
    const int w   = tid >> 5;
    const int l   = tid & 31;
    const int p0  = l*4;
    const int b   = blockIdx.x >> 4;
    const int n0  = (blockIdx.x & 15) << 7;

    for (int i = tid; i < 128; i += 256) { int c=i>>4, o=i&15; wW1t[i] = dk_g1[o]*dk_W1[o*8+c]; }
    if (tid < 16) wb1[tid] = dk_g1[tid]*dk_b1[tid] + dk_be1[tid];
    for (int i = tid; i < 512; i += 256) { int c=i>>5, o=i&31; wW2t[i] = dk_W2[o*16+c]; }
    if (tid < 32) wb2[tid] = dk_b2[tid];
    for (int i = tid; i < 512; i += 256) {
        int c = i >> 5, o = i & 31;
        float s = 0.f;
        #pragma unroll
        for (int j = 0; j < 32; j++) s += ff_W1[o*64 + j] * dk_W2[j*16 + c];
        wAh[c*32 + o] = ff_g1[o] * s;
    }
    if (tid < 32) {
        float s = 0.f;
        #pragma unroll
        for (int j = 0; j < 32; j++) s += ff_W1[tid*64 + j] * dk_b2[j];
        wbf[tid] = ff_be1[tid] + ff_g1[tid] * s;
    }
    for (int i = tid; i < 1024; i += 256) { int c=i>>5, o=i&31; wBg[i] = ff_g1[o]*ff_W1[o*64+32+c]; }
    for (int i = tid; i < 2048; i += 256) { int c=i>>6, o=i&63; wF2t[i] = ff_W2[o*32+c]; }
    if (tid < 64) wab[tid] = act_b[tid];
    for (int i = tid; i < 4096; i += 256) { int c=i>>6, o=i&63; wWEt[i] = edge_g[o]*edge_W[o*128+c]; }
    if (tid < 128) {
        const float* ap = appf + (((size_t)b*NN + n0 + tid)*NK + 0)*8;
        float4 a0 = *(const float4*)ap;
        float4 a1 = *(const float4*)(ap + 4);
        t_in[0*128+tid]=a0.x; t_in[1*128+tid]=a0.y; t_in[2*128+tid]=a0.z; t_in[3*128+tid]=a0.w;
        t_in[4*128+tid]=a1.x; t_in[5*128+tid]=a1.y; t_in[6*128+tid]=a1.z; t_in[7*128+tid]=a1.w;
    }
    __syncthreads();

    float mx[4][8];
    #pragma unroll
    for (int pp = 0; pp < 4; pp++)
        #pragma unroll
        for (int oo = 0; oo < 8; oo++) mx[pp][oo] = -1e30f;

    #pragma unroll 1
    for (int k = 0; k < NK; k++) {
        float4 gl[4];
        int idxr = 0;
        {
            const float* src = g_glT + (((size_t)b*NK + k)*32)*NN + n0;
            #pragma unroll
            for (int u = 0; u < 4; u++) {
                int f = (tid + u*256)*4;
                int c = f >> 7, col = f & 127;
                gl[u] = *(const float4*)&src[c*NN + col];
            }
        }
        if (tid < 128) idxr = g_idxT[((size_t)b*NK + k)*NN + n0 + tid];

        // GEMM1: dk1 [16x128], K=8
        {
            const int o0 = w*2;
            const u64 bias = *(const u64*)&wb1[o0];
            u64 a0 = bias, a1 = bias, a2 = bias, a3 = bias;
            #pragma unroll
            for (int c = 0; c < 8; c++) {
                u64 wv = *(const u64*)&wW1t[c*16 + o0];
                float4 bv = *(float4*)&t_in[c*128 + p0];
                ffma2(a0, wv, f2pack(bv.x, bv.x));
                ffma2(a1, wv, f2pack(bv.y, bv.y));
                ffma2(a2, wv, f2pack(bv.z, bv.z));
                ffma2(a3, wv, f2pack(bv.w, bv.w));
            }
            float l0,h0,l1,h1,l2,h2,l3,h3;
            f2unpack(a0,l0,h0); f2unpack(a1,l1,h1); f2unpack(a2,l2,h2); f2unpack(a3,l3,h3);
            *(float4*)&t_h[o0*128 + p0]     = make_float4(fmaxf(l0,0.f), fmaxf(l1,0.f), fmaxf(l2,0.f), fmaxf(l3,0.f));
            *(float4*)&t_h[(o0+1)*128 + p0] = make_float4(fmaxf(h0,0.f), fmaxf(h1,0.f), fmaxf(h2,0.f), fmaxf(h3,0.f));
        }
        {
            #pragma unroll
            for (int u = 0; u < 4; u++) {
                int f = (tid + u*256)*4;
                int c = f >> 7, col = f & 127;
                *(float4*)&t_rif[(32+c)*128 + col] = gl[u];
            }
        }
        if (tid < 128) s_idx[tid] = idxr;
        __syncthreads();   // A

        float4 a0n, a1n;
        if (tid < 128) {
            int kn = (k+1 < NK) ? k+1 : k;
            const float* ap = appf + (((size_t)b*NN + n0 + tid)*NK + kn)*8;
            a0n = *(const float4*)ap;
            a1n = *(const float4*)(ap + 4);
        }

        // GEMM2: dk2 [32x128], K=16
        {
            const int o0 = w*4;
            ulonglong2 bi = *(const ulonglong2*)&wb2[o0];
            u64 acc[4][2];
            #pragma unroll
            for (int pp = 0; pp < 4; pp++) { acc[pp][0] = bi.x; acc[pp][1] = bi.y; }
            #pragma unroll
            for (int c = 0; c < 16; c++) {
                ulonglong2 wv = *(const ulonglong2*)&wW2t[c*32 + o0];
                float4 bv = *(float4*)&t_h[c*128 + p0];
                u64 bx = f2pack(bv.x,bv.x), by = f2pack(bv.y,bv.y);
                u64 bz = f2pack(bv.z,bv.z), bw = f2pack(bv.w,bv.w);
                ffma2(acc[0][0], wv.x, bx); ffma2(acc[0][1], wv.y, bx);
                ffma2(acc[1][0], wv.x, by); ffma2(acc[1][1], wv.y, by);
                ffma2(acc[2][0], wv.x, bz); ffma2(acc[2][1], wv.y, bz);
                ffma2(acc[3][0], wv.x, bw); ffma2(acc[3][1], wv.y, bw);
            }
            #pragma unroll
            for (int pr = 0; pr < 2; pr++) {
                float l0,h0,l1,h1,l2,h2,l3,h3;
                f2unpack(acc[0][pr],l0,h0); f2unpack(acc[1][pr],l1,h1);
                f2unpack(acc[2][pr],l2,h2); f2unpack(acc[3][pr],l3,h3);
                *(float4*)&t_rif[(o0+2*pr)*128 + p0]   = make_float4(l0,l1,l2,l3);
                *(float4*)&t_rif[(o0+2*pr+1)*128 + p0] = make_float4(h0,h1,h2,h3);
            }
        }
        if (tid < 128) {
            t_in[0*128+tid]=a0n.x; t_in[1*128+tid]=a0n.y; t_in[2*128+tid]=a0n.z; t_in[3*128+tid]=a0n.w;
            t_in[4*128+tid]=a1n.x; t_in[5*128+tid]=a1n.y; t_in[6*128+tid]=a1n.z; t_in[7*128+tid]=a1n.w;
        }
        // GEMM3 (folded): att = wAh@h (16c) + wBg@glf (32c) + wbf
        {
            const int o0 = w*4;
            ulonglong2 bi = *(const ulonglong2*)&wbf[o0];
            u64 acc[4][2];
            #pragma unroll
            for (int pp = 0; pp < 4; pp++) { acc[pp][0] = bi.x; acc[pp][1] = bi.y; }
            #pragma unroll 4
            for (int c = 0; c < 16; c++) {
                ulonglong2 wv = *(const ulonglong2*)&wAh[c*32 + o0];
                float4 bv = *(float4*)&t_h[c*128 + p0];
                u64 bx = f2pack(bv.x,bv.x), by = f2pack(bv.y,bv.y);
                u64 bz = f2pack(bv.z,bv.z), bw = f2pack(bv.w,bv.w);
                ffma2(acc[0][0], wv.x, bx); ffma2(acc[0][1], wv.y, bx);
                ffma2(acc[1][0], wv.x, by); ffma2(acc[1][1], wv.y, by);
                ffma2(acc[2][0], wv.x, bz); ffma2(acc[2][1], wv.y, bz);
                ffma2(acc[3][0], wv.x, bw); ffma2(acc[3][1], wv.y, bw);
            }
            #pragma unroll 4
            for (int c = 0; c < 32; c++) {
                ulonglong2 wv = *(const ulonglong2*)&wBg[c*32 + o0];
                float4 bv = *(float4*)&t_rif[(32+c)*128 + p0];
                u64 bx = f2pack(bv.x,bv.x), by = f2pack(bv.y,bv.y);
                u64 bz = f2pack(bv.z,bv.z), bw = f2pack(bv.w,bv.w);
                ffma2(acc[0][0], wv.x, bx); ffma2(acc[0][1], wv.y, bx);
                ffma2(acc[1][0], wv.x, by); ffma2(acc[1][1], wv.y, by);
                ffma2(acc[2][0], wv.x, bz); ffma2(acc[2][1], wv.y, bz);
                ffma2(acc[3][0], wv.x, bw); ffma2(acc[3][1], wv.y, bw);
            }
            #pragma unroll
            for (int pr = 0; pr < 2; pr++) {
                float l0,h0,l1,h1,l2,h2,l3,h3;
                f2unpack(acc[0][pr],l0,h0); f2unpack(acc[1][pr],l1,h1);
                f2unpack(acc[2][pr],l2,h2); f2unpack(acc[3][pr],l3,h3);
                *(float4*)&t_att[(o0+2*pr)*128 + p0] =
                    make_float4(LEAKY(l0),LEAKY(l1),LEAKY(l2),LEAKY(l3));
                *(float4*)&t_att[(o0+2*pr+1)*128 + p0] =
                    make_float4(LEAKY(h0),LEAKY(h1),LEAKY(h2),LEAKY(h3));
            }
        }
        __syncthreads();   // B

        // GEMM4: ff2 [64x128], K=32; sigmoid; gate in place
        {
            const int o0 = w*8;
            u64 acc[4][4];
            #pragma unroll
            for (int pp = 0; pp < 4; pp++)
                #pragma unroll
                for (int pr = 0; pr < 4; pr++) acc[pp][pr] = 0ull;
            #pragma unroll 4
            for (int c = 0; c < 32; c++) {
                ulonglong2 wA = *(const ulonglong2*)&wF2t[c*64 + o0];
                ulonglong2 wB = *(const ulonglong2*)&wF2t[c*64 + o0 + 4];
                float4 bv = *(float4*)&t_att[c*128 + p0];
                u64 bx = f2pack(bv.x,bv.x), by = f2pack(bv.y,bv.y);
                u64 bz = f2pack(bv.z,bv.z), bw = f2pack(bv.w,bv.w);
                ffma2(acc[0][0], wA.x, bx); ffma2(acc[0][1], wA.y, bx);
                ffma2(acc[0][2], wB.x, bx); ffma2(acc[0][3], wB.y, bx);
                ffma2(acc[1][0], wA.x, by); ffma2(acc[1][1], wA.y, by);
                ffma2(acc[1][2], wB.x, by); ffma2(acc[1][3], wB.y, by);
                ffma2(acc[2][0], wA.x, bz); ffma2(acc[2][1], wA.y, bz);
                ffma2(acc[2][2], wB.x, bz); ffma2(acc[2][3], wB.y, bz);
                ffma2(acc[3][0], wA.x, bw); ffma2(acc[3][1], wA.y, bw);
                ffma2(acc[3][2], wB.x, bw); ffma2(acc[3][3], wB.y, bw);
            }
            #pragma unroll
            for (int hh = 0; hh < 2; hh++) {
                float sg[4][4];
                float bxv[4][4];
                #pragma unroll
                for (int pp = 0; pp < 4; pp++) {
                    float lo, hi;
                    f2unpack(acc[pp][2*hh],   lo, hi);
                    sg[pp][0] = 1.f/(1.f + __expf(-lo));
                    sg[pp][1] = 1.f/(1.f + __expf(-hi));
                    f2unpack(acc[pp][2*hh+1], lo, hi);
                    sg[pp][2] = 1.f/(1.f + __expf(-lo));
                    sg[pp][3] = 1.f/(1.f + __expf(-hi));
                    int j = s_idx[p0 + pp];
                    float4 gv = *(const float4*)(g_bxT + ((size_t)b*NN + j)*64 + o0 + 4*hh);
                    bxv[pp][0] = gv.x; bxv[pp][1] = gv.y; bxv[pp][2] = gv.z; bxv[pp][3] = gv.w;
                }
                #pragma unroll
                for (int oo = 0; oo < 4; oo++) {
                    int row = o0 + 4*hh + oo;
                    float ab = wab[row];
                    float4 rv = *(float4*)&t_rif[row*128 + p0];
                    rv.x = fmaxf(rv.x * sg[0][oo] * bxv[0][oo] + ab, 0.f);
                    rv.y = fmaxf(rv.y * sg[1][oo] * bxv[1][oo] + ab, 0.f);
                    rv.z = fmaxf(rv.z * sg[2][oo] * bxv[2][oo] + ab, 0.f);
                    rv.w = fmaxf(rv.w * sg[3][oo] * bxv[3][oo] + ab, 0.f);
                    *(float4*)&t_rif[row*128 + p0] = rv;
                }
            }
        }
        __syncthreads();   // C

        // GEMM5: edge [64x128], K=64; running max
        {
            const int o0 = w*8;
            u64 acc[4][4];
            #pragma unroll
            for (int pp = 0; pp < 4; pp++)
                #pragma unroll
                for (int pr = 0; pr < 4; pr++) acc[pp][pr] = 0ull;
            #pragma unroll 4
            for (int c = 0; c < 64; c++) {
                ulonglong2 wA = *(const ulonglong2*)&wWEt[c*64 + o0];
                ulonglong2 wB = *(const ulonglong2*)&wWEt[c*64 + o0 + 4];
                float4 bv = *(float4*)&t_rif[c*128 + p0];
                u64 bx = f2pack(bv.x,bv.x), by = f2pack(bv.y,bv.y);
                u64 bz = f2pack(bv.z,bv.z), bw = f2pack(bv.w,bv.w);
                ffma2(acc[0][0], wA.x, bx); ffma2(acc[0][1], wA.y, bx);
                ffma2(acc[0][2], wB.x, bx); ffma2(acc[0][3], wB.y, bx);
                ffma2(acc[1][0], wA.x, by); ffma2(acc[1][1], wA.y, by);
                ffma2(acc[1][2], wB.x, by); ffma2(acc[1][3], wB.y, by);
                ffma2(acc[2][0], wA.x, bz); ffma2(acc[2][1], wA.y, bz);
                ffma2(acc[2][2], wB.x, bz); ffma2(acc[2][3], wB.y, bz);
                ffma2(acc[3][0], wA.x, bw); ffma2(acc[3][1], wA.y, bw);
                ffma2(acc[3][2], wB.x, bw); ffma2(acc[3][3], wB.y, bw);
            }
            #pragma unroll
            for (int pp = 0; pp < 4; pp++) {
                #pragma unroll
                for (int pr = 0; pr < 4; pr++) {
                    float lo, hi;
                    f2unpack(acc[pp][pr], lo, hi);
                    mx[pp][2*pr]   = fmaxf(mx[pp][2*pr],   lo);
                    mx[pp][2*pr+1] = fmaxf(mx[pp][2*pr+1], hi);
                }
            }
        }
        __syncthreads();   // D
    }

    // epilogue: out = leaky(mx + cst)
    {
        const int o0 = w*8;
        #pragma unroll
        for (int hh = 0; hh < 2; hh++) {
            float cc[4][4];
            #pragma unroll
            for (int pp = 0; pp < 4; pp++) {
                float4 cv = *(const float4*)(g_cst + ((size_t)b*NN + n0 + p0 + pp)*64 + o0 + 4*hh);
                cc[pp][0]=cv.x; cc[pp][1]=cv.y; cc[pp][2]=cv.z; cc[pp][3]=cv.w;
            }
            #pragma unroll
            for (int oo = 0; oo < 4; oo++) {
                int row = o0 + 4*hh + oo;
                float4 v;
                v.x = LEAKY(mx[0][4*hh+oo] + cc[0][oo]);
                v.y = LEAKY(mx[1][4*hh+oo] + cc[1][oo]);
                v.z = LEAKY(mx[2][4*hh+oo] + cc[2][oo]);
                v.w = LEAKY(mx[3][4*hh+oo] + cc[3][oo]);
                *(float4*)&out[((size_t)b*64 + row)*NN + n0 + p0] = v;
            }
        }
    }
}

// =====================================================================
extern "C" void kernel_launch(void* const* d_in, const int* in_sizes, int n_in,
                              void* d_out, int out_size)
{
    const float* pos     = (const float*)d_in[0];
    const float* x       = (const float*)d_in[1];
    const float* glf     = (const float*)d_in[2];
    const float* appf    = (const float*)d_in[3];
    const float* basis_W = (const float*)d_in[4];
    const float* dk_W1   = (const float*)d_in[5];
    const float* dk_b1   = (const float*)d_in[6];
    const float* dk_g1   = (const float*)d_in[7];
    const float* dk_be1  = (const float*)d_in[8];
    const float* dk_W2   = (const float*)d_in[9];
    const float* dk_b2   = (const float*)d_in[10];
    const float* act_g   = (const float*)d_in[11];
    const float* act_b   = (const float*)d_in[12];
    const float* ff_W1   = (const float*)d_in[13];
    const float* ff_g1   = (const float*)d_in[14];
    const float* ff_be1  = (const float*)d_in[15];
    const float* ff_W2   = (const float*)d_in[16];
    const float* edge_W  = (const float*)d_in[17];
    const float* edge_g  = (const float*)d_in[18];
    const float* edge_be = (const float*)d_in[19];
    float* out = (float*)d_out;

    knn_kernel<<<dim3(NN/32, NB), 256>>>(pos);
    prep_kernel<<<(NB*NN)/128, 128>>>(x, basis_W, edge_W, act_g, edge_g, edge_be);
    tr_kernel<<<dim3(NN/64, 32, NB), 256>>>(glf);

    const int smem_bytes = (128+16+512+32+512+32+1024+2048+64+4096 + 1024+2048+8192+4096 + 128) * (int)sizeof(float);
    cudaFuncSetAttribute(main_kernel, cudaFuncAttributeMaxDynamicSharedMemorySize, smem_bytes);
    main_kernel<<<NB*NN/128, 256, smem_bytes>>>(appf,
                                                dk_W1, dk_b1, dk_g1, dk_be1,
                                                dk_W2, dk_b2, act_b,
                                                ff_W1, ff_g1, ff_be1, ff_W2,
                                                edge_W, edge_g, out);
}

// round 15
// speedup vs baseline: 1.0449x; 1.0449x over previous
#include <cuda_runtime.h>
#include <math.h>

#define NB 16
#define NN 2048
#define NK 20
#define NC 64

typedef unsigned long long u64;

// ---- scratch (static __device__, allocation-free) ----
__device__ int   g_idxT[NB*NK*NN];          // knn indices, [b][k][n]
__device__ float g_bxT [NB*NN*NC];          // act_g * (basis_W @ x), point-major [p][c]
__device__ float g_cst [NB*NN*NC];          // edge_g*((We2-We1)@x) + edge_be, [p][o]
__device__ float g_glT [NB*NK*32*NN];       // glf transposed to [b][k][c][n]

// ---- packed f32x2 helpers (Blackwell FFMA2) ----
__device__ __forceinline__ u64 f2pack(float lo, float hi) {
    u64 r; asm("mov.b64 %0, {%1, %2};" : "=l"(r) : "f"(lo), "f"(hi)); return r;
}
__device__ __forceinline__ void f2unpack(u64 v, float& lo, float& hi) {
    asm("mov.b64 {%0, %1}, %2;" : "=f"(lo), "=f"(hi) : "l"(v));
}
__device__ __forceinline__ void ffma2(u64& d, u64 a, u64 b) {
    asm("fma.rn.f32x2 %0, %1, %2, %3;" : "=l"(d) : "l"(a), "l"(b), "l"(d));
}

#define LEAKY(v) ((v) > 0.f ? (v) : 0.2f*(v))

// =====================================================================
// MEGA kernel: knn (blocks [0,1024)) + glf transpose (blocks [1024,5120)).
// knn blocks are scheduled first and dominate; tr blocks backfill as knn
// CTAs retire, hiding the transpose entirely under knn's runtime.
// knn branch == round-10 best-measured version (single query/warp-step,
// cmp-guard insert; ties: ascending-m + strict > == lax.top_k; self
// excluded via select, reference's dropped top-1 is self pd=0 bit-exact).
// =====================================================================
__global__ void __launch_bounds__(256)
mega_kernel(const float* __restrict__ pos, const float* __restrict__ glf)
{
    extern __shared__ float smd[];
    const int tid = threadIdx.x;

    if (blockIdx.x < 1024) {
        // ================= KNN =================
        float4* sp = (float4*)smd;                 // 2048 float4 = 32KB
        const int b    = blockIdx.x >> 6;
        const int qc   = blockIdx.x & 63;
        const int w    = tid >> 5;
        const int lane = tid & 31;
        const float* pb = pos + (size_t)b*3*NN;
        for (int m = tid; m < NN; m += 256) {
            float xx = pb[m], yy = pb[NN + m], zz = pb[2*NN + m];
            sp[m] = make_float4(xx, yy, zz, xx*xx + yy*yy + zz*zz);
        }
        __syncthreads();

        const int qbase = qc*32 + w*4;
        #pragma unroll 1
        for (int qi = 0; qi < 4; qi++) {
            const int q = qbase + qi;
            const float4 pq = sp[q];
            float v = -1e30f;
            int   idx = 0;

            #pragma unroll 1
            for (int blk = 0; blk < NN; blk += 32) {
                const int m = blk + lane;
                float4 pm = sp[m];
                float pd = 2.0f*(pq.x*pm.x + pq.y*pm.y + pq.z*pm.z) - pq.w - pm.w;
                pd = (m == q) ? -1e30f : pd;
                float t20 = __shfl_sync(0xFFFFFFFFu, v, 19);
                unsigned mask = __ballot_sync(0xFFFFFFFFu, pd > t20);
                while (mask) {
                    int src = __ffs((int)mask) - 1;
                    float pdv = __shfl_sync(0xFFFFFFFFu, pd, src);
                    mask &= mask - 1;
                    unsigned cmp = __ballot_sync(0xFFFFFFFFu, pdv > v) & 0xFFFFFu;
                    if (cmp) {
                        int pos_ = __ffs((int)cmp) - 1;
                        float nv = __shfl_up_sync(0xFFFFFFFFu, v, 1);
                        int  nid = __shfl_up_sync(0xFFFFFFFFu, idx, 1);
                        if (lane > pos_)  { v = nv;  idx = nid; }
                        if (lane == pos_) { v = pdv; idx = blk + src; }
                    }
                }
            }
            if (lane < NK)
                g_idxT[((size_t)b*NK + lane)*NN + q] = idx;
        }
    } else {
        // ================= glf transpose: (B,32,N,K) -> [b][k][c][n] ====
        // block handles 4 c-slices x 64 n of one b. 4096 blocks total.
        const int t  = blockIdx.x - 1024;          // 0..4095
        const int b  = t >> 8;
        const int r  = t & 255;
        const int cg = r >> 5;                     // 0..7 (c-group of 4)
        const int n0 = (r & 31) << 6;              // 0..1984
        #pragma unroll 1
        for (int cc = 0; cc < 4; cc++) {
            const int c = cg*4 + cc;
            float* s = smd + cc*(64*21);
            const float* in = glf + (((size_t)b*32 + c)*NN + n0) * NK;
            #pragma unroll
            for (int u = 0; u < 5; u++) {
                int f = tid + u*256;               // 1280 total
                int n = f / 20, k = f % 20;
                s[n*21 + k] = in[f];
            }
        }
        __syncthreads();
        #pragma unroll 1
        for (int cc = 0; cc < 4; cc++) {
            const int c = cg*4 + cc;
            float* s = smd + cc*(64*21);
            #pragma unroll
            for (int u = 0; u < 5; u++) {
                int f = tid + u*256;
                int k = f >> 6, n = f & 63;
                g_glT[(((size_t)b*NK + k)*32 + c)*NN + n0 + n] = s[n*21 + k];
            }
        }
    }
}

// =====================================================================
// prep (unchanged; kept separate so its register pressure cannot
// depress knn's occupancy)
// =====================================================================
__global__ void prep_kernel(const float* __restrict__ x,
                            const float* __restrict__ basis_W,
                            const float* __restrict__ edge_W,
                            const float* __restrict__ act_g,
                            const float* __restrict__ edge_g,
                            const float* __restrict__ edge_be)
{
    __shared__ float sB[64*64];
    __shared__ float sD[64*64];
    __shared__ float sag[64], seg[64], seb[64];
    const int tid = threadIdx.x;
    for (int i = tid; i < 4096; i += blockDim.x) {
        sB[i] = basis_W[i];
        int o = i >> 6, c = i & 63;
        sD[i] = edge_W[o*128 + 64 + c] - edge_W[o*128 + c];
    }
    for (int i = tid; i < 64; i += blockDim.x) {
        sag[i] = act_g[i]; seg[i] = edge_g[i]; seb[i] = edge_be[i];
    }
    __syncthreads();

    const int p = blockIdx.x * blockDim.x + tid;
    const int b = p / NN, n = p % NN;
    const float* xp = x + (size_t)b*64*NN + n;
    float xv[64];
    #pragma unroll
    for (int c = 0; c < 64; c++) xv[c] = xp[(size_t)c*NN];

    float* bo = g_bxT + (size_t)p*64;
    #pragma unroll 4
    for (int o = 0; o < 64; o++) {
        float acc = 0.f;
        #pragma unroll
        for (int c = 0; c < 64; c++) acc += sB[o*64+c]*xv[c];
        bo[o] = acc * sag[o];
    }
    float* co = g_cst + (size_t)p*64;
    #pragma unroll 4
    for (int o = 0; o < 64; o++) {
        float acc = 0.f;
        #pragma unroll
        for (int c = 0; c < 64; c++) acc += sD[o*64+c]*xv[c];
        co[o] = acc*seg[o] + seb[o];
    }
}

// =====================================================================
// main fused kernel (round-10 best: 337us): 256 thr, 128-pt tile,
// 4 pts/thread, dk2-into-ff1 fold, deferred STS, appf pipelining.
// =====================================================================
__global__ void __launch_bounds__(256, 2)
main_kernel(const float* __restrict__ appf,
            const float* __restrict__ dk_W1, const float* __restrict__ dk_b1,
            const float* __restrict__ dk_g1, const float* __restrict__ dk_be1,
            const float* __restrict__ dk_W2, const float* __restrict__ dk_b2,
            const float* __restrict__ act_b,
            const float* __restrict__ ff_W1, const float* __restrict__ ff_g1,
            const float* __restrict__ ff_be1, const float* __restrict__ ff_W2,
            const float* __restrict__ edge_W, const float* __restrict__ edge_g,
            float* __restrict__ out)
{
    extern __shared__ float sm[];
    float* wW1t = sm;             // [8][16]   128
    float* wb1  = wW1t + 128;     // 16
    float* wW2t = wb1  + 16;      // [16][32]  512
    float* wb2  = wW2t + 512;     // 32
    float* wAh  = wb2  + 32;      // [16][32]  512  folded (g*W1a)@W2, [c][o]
    float* wbf  = wAh  + 512;     // 32
    float* wBg  = wbf  + 32;      // [32][32]  1024 g*W1[:,32:], [c][o]
    float* wF2t = wBg  + 1024;    // [32][64]  2048
    float* wab  = wF2t + 2048;    // 64
    float* wWEt = wab  + 64;      // [64][64]  4096
    float* t_in = wWEt + 4096;    // [8][128]  1024
    float* t_h  = t_in + 1024;    // [16][128] 2048
    float* t_rif= t_h  + 2048;    // [64][128] 8192
    float* t_att= t_rif+ 8192;    // [32][128] 4096
    int*   s_idx= (int*)(t_att + 4096);   // 128

    const int tid = threadIdx.x;
    const int w   = tid >> 5;
    const int l   = tid & 31;
    const int p0  = l*4;
    const int b   = blockIdx.x >> 4;
    const int n0  = (blockIdx.x & 15) << 7;

    for (int i = tid; i < 128; i += 256) { int c=i>>4, o=i&15; wW1t[i] = dk_g1[o]*dk_W1[o*8+c]; }
    if (tid < 16) wb1[tid] = dk_g1[tid]*dk_b1[tid] + dk_be1[tid];
    for (int i = tid; i < 512; i += 256) { int c=i>>5, o=i&31; wW2t[i] = dk_W2[o*16+c]; }
    if (tid < 32) wb2[tid] = dk_b2[tid];
    for (int i = tid; i < 512; i += 256) {
        int c = i >> 5, o = i & 31;
        float s = 0.f;
        #pragma unroll
        for (int j = 0; j < 32; j++) s += ff_W1[o*64 + j] * dk_W2[j*16 + c];
        wAh[c*32 + o] = ff_g1[o] * s;
    }
    if (tid < 32) {
        float s = 0.f;
        #pragma unroll
        for (int j = 0; j < 32; j++) s += ff_W1[tid*64 + j] * dk_b2[j];
        wbf[tid] = ff_be1[tid] + ff_g1[tid] * s;
    }
    for (int i = tid; i < 1024; i += 256) { int c=i>>5, o=i&31; wBg[i] = ff_g1[o]*ff_W1[o*64+32+c]; }
    for (int i = tid; i < 2048; i += 256) { int c=i>>6, o=i&63; wF2t[i] = ff_W2[o*32+c]; }
    if (tid < 64) wab[tid] = act_b[tid];
    for (int i = tid; i < 4096; i += 256) { int c=i>>6, o=i&63; wWEt[i] = edge_g[o]*edge_W[o*128+c]; }
    if (tid < 128) {
        const float* ap = appf + (((size_t)b*NN + n0 + tid)*NK + 0)*8;
        float4 a0 = *(const float4*)ap;
        float4 a1 = *(const float4*)(ap + 4);
        t_in[0*128+tid]=a0.x; t_in[1*128+tid]=a0.y; t_in[2*128+tid]=a0.z; t_in[3*128+tid]=a0.w;
        t_in[4*128+tid]=a1.x; t_in[5*128+tid]=a1.y; t_in[6*128+tid]=a1.z; t_in[7*128+tid]=a1.w;
    }
    __syncthreads();

    float mx[4][8];
    #pragma unroll
    for (int pp = 0; pp < 4; pp++)
        #pragma unroll
        for (int oo = 0; oo < 8; oo++) mx[pp][oo] = -1e30f;

    #pragma unroll 1
    for (int k = 0; k < NK; k++) {
        float4 gl[4];
        int idxr = 0;
        {
            const float* src = g_glT + (((size_t)b*NK + k)*32)*NN + n0;
            #pragma unroll
            for (int u = 0; u < 4; u++) {
                int f = (tid + u*256)*4;
                int c = f >> 7, col = f & 127;
                gl[u] = *(const float4*)&src[c*NN + col];
            }
        }
        if (tid < 128) idxr = g_idxT[((size_t)b*NK + k)*NN + n0 + tid];

        // GEMM1: dk1 [16x128], K=8
        {
            const int o0 = w*2;
            const u64 bias = *(const u64*)&wb1[o0];
            u64 a0 = bias, a1 = bias, a2 = bias, a3 = bias;
            #pragma unroll
            for (int c = 0; c < 8; c++) {
                u64 wv = *(const u64*)&wW1t[c*16 + o0];
                float4 bv = *(float4*)&t_in[c*128 + p0];
                ffma2(a0, wv, f2pack(bv.x, bv.x));
                ffma2(a1, wv, f2pack(bv.y, bv.y));
                ffma2(a2, wv, f2pack(bv.z, bv.z));
                ffma2(a3, wv, f2pack(bv.w, bv.w));
            }
            float l0,h0,l1,h1,l2,h2,l3,h3;
            f2unpack(a0,l0,h0); f2unpack(a1,l1,h1); f2unpack(a2,l2,h2); f2unpack(a3,l3,h3);
            *(float4*)&t_h[o0*128 + p0]     = make_float4(fmaxf(l0,0.f), fmaxf(l1,0.f), fmaxf(l2,0.f), fmaxf(l3,0.f));
            *(float4*)&t_h[(o0+1)*128 + p0] = make_float4(fmaxf(h0,0.f), fmaxf(h1,0.f), fmaxf(h2,0.f), fmaxf(h3,0.f));
        }
        {
            #pragma unroll
            for (int u = 0; u < 4; u++) {
                int f = (tid + u*256)*4;
                int c = f >> 7, col = f & 127;
                *(float4*)&t_rif[(32+c)*128 + col] = gl[u];
            }
        }
        if (tid < 128) s_idx[tid] = idxr;
        __syncthreads();   // A

        float4 a0n, a1n;
        if (tid < 128) {
            int kn = (k+1 < NK) ? k+1 : k;
            const float* ap = appf + (((size_t)b*NN + n0 + tid)*NK + kn)*8;
            a0n = *(const float4*)ap;
            a1n = *(const float4*)(ap + 4);
        }

        // GEMM2: dk2 [32x128], K=16
        {
            const int o0 = w*4;
            ulonglong2 bi = *(const ulonglong2*)&wb2[o0];
            u64 acc[4][2];
            #pragma unroll
            for (int pp = 0; pp < 4; pp++) { acc[pp][0] = bi.x; acc[pp][1] = bi.y; }
            #pragma unroll
            for (int c = 0; c < 16; c++) {
                ulonglong2 wv = *(const ulonglong2*)&wW2t[c*32 + o0];
                float4 bv = *(float4*)&t_h[c*128 + p0];
                u64 bx = f2pack(bv.x,bv.x), by = f2pack(bv.y,bv.y);
                u64 bz = f2pack(bv.z,bv.z), bw = f2pack(bv.w,bv.w);
                ffma2(acc[0][0], wv.x, bx); ffma2(acc[0][1], wv.y, bx);
                ffma2(acc[1][0], wv.x, by); ffma2(acc[1][1], wv.y, by);
                ffma2(acc[2][0], wv.x, bz); ffma2(acc[2][1], wv.y, bz);
                ffma2(acc[3][0], wv.x, bw); ffma2(acc[3][1], wv.y, bw);
            }
            #pragma unroll
            for (int pr = 0; pr < 2; pr++) {
                float l0,h0,l1,h1,l2,h2,l3,h3;
                f2unpack(acc[0][pr],l0,h0); f2unpack(acc[1][pr],l1,h1);
                f2unpack(acc[2][pr],l2,h2); f2unpack(acc[3][pr],l3,h3);
                *(float4*)&t_rif[(o0+2*pr)*128 + p0]   = make_float4(l0,l1,l2,l3);
                *(float4*)&t_rif[(o0+2*pr+1)*128 + p0] = make_float4(h0,h1,h2,h3);
            }
        }
        if (tid < 128) {
            t_in[0*128+tid]=a0n.x; t_in[1*128+tid]=a0n.y; t_in[2*128+tid]=a0n.z; t_in[3*128+tid]=a0n.w;
            t_in[4*128+tid]=a1n.x; t_in[5*128+tid]=a1n.y; t_in[6*128+tid]=a1n.z; t_in[7*128+tid]=a1n.w;
        }
        // GEMM3 (folded): att = wAh@h (16c) + wBg@glf (32c) + wbf
        {
            const int o0 = w*4;
            ulonglong2 bi = *(const ulonglong2*)&wbf[o0];
            u64 acc[4][2];
            #pragma unroll
            for (int pp = 0; pp < 4; pp++) { acc[pp][0] = bi.x; acc[pp][1] = bi.y; }
            #pragma unroll 4
            for (int c = 0; c < 16; c++) {
                ulonglong2 wv = *(const ulonglong2*)&wAh[c*32 + o0];
                float4 bv = *(float4*)&t_h[c*128 + p0];
                u64 bx = f2pack(bv.x,bv.x), by = f2pack(bv.y,bv.y);
                u64 bz = f2pack(bv.z,bv.z), bw = f2pack(bv.w,bv.w);
                ffma2(acc[0][0], wv.x, bx); ffma2(acc[0][1], wv.y, bx);
                ffma2(acc[1][0], wv.x, by); ffma2(acc[1][1], wv.y, by);
                ffma2(acc[2][0], wv.x, bz); ffma2(acc[2][1], wv.y, bz);
                ffma2(acc[3][0], wv.x, bw); ffma2(acc[3][1], wv.y, bw);
            }
            #pragma unroll 4
            for (int c = 0; c < 32; c++) {
                ulonglong2 wv = *(const ulonglong2*)&wBg[c*32 + o0];
                float4 bv = *(float4*)&t_rif[(32+c)*128 + p0];
                u64 bx = f2pack(bv.x,bv.x), by = f2pack(bv.y,bv.y);
                u64 bz = f2pack(bv.z,bv.z), bw = f2pack(bv.w,bv.w);
                ffma2(acc[0][0], wv.x, bx); ffma2(acc[0][1], wv.y, bx);
                ffma2(acc[1][0], wv.x, by); ffma2(acc[1][1], wv.y, by);
                ffma2(acc[2][0], wv.x, bz); ffma2(acc[2][1], wv.y, bz);
                ffma2(acc[3][0], wv.x, bw); ffma2(acc[3][1], wv.y, bw);
            }
            #pragma unroll
            for (int pr = 0; pr < 2; pr++) {
                float l0,h0,l1,h1,l2,h2,l3,h3;
                f2unpack(acc[0][pr],l0,h0); f2unpack(acc[1][pr],l1,h1);
                f2unpack(acc[2][pr],l2,h2); f2unpack(acc[3][pr],l3,h3);
                *(float4*)&t_att[(o0+2*pr)*128 + p0] =
                    make_float4(LEAKY(l0),LEAKY(l1),LEAKY(l2),LEAKY(l3));
                *(float4*)&t_att[(o0+2*pr+1)*128 + p0] =
                    make_float4(LEAKY(h0),LEAKY(h1),LEAKY(h2),LEAKY(h3));
            }
        }
        __syncthreads();   // B

        // GEMM4: ff2 [64x128], K=32; sigmoid; gate in place
        {
            const int o0 = w*8;
            u64 acc[4][4];
            #pragma unroll
            for (int pp = 0; pp < 4; pp++)
                #pragma unroll
                for (int pr = 0; pr < 4; pr++) acc[pp][pr] = 0ull;
            #pragma unroll 4
            for (int c = 0; c < 32; c++) {
                ulonglong2 wA = *(const ulonglong2*)&wF2t[c*64 + o0];
                ulonglong2 wB = *(const ulonglong2*)&wF2t[c*64 + o0 + 4];
                float4 bv = *(float4*)&t_att[c*128 + p0];
                u64 bx = f2pack(bv.x,bv.x), by = f2pack(bv.y,bv.y);
                u64 bz = f2pack(bv.z,bv.z), bw = f2pack(bv.w,bv.w);
                ffma2(acc[0][0], wA.x, bx); ffma2(acc[0][1], wA.y, bx);
                ffma2(acc[0][2], wB.x, bx); ffma2(acc[0][3], wB.y, bx);
                ffma2(acc[1][0], wA.x, by); ffma2(acc[1][1], wA.y, by);
                ffma2(acc[1][2], wB.x, by); ffma2(acc[1][3], wB.y, by);
                ffma2(acc[2][0], wA.x, bz); ffma2(acc[2][1], wA.y, bz);
                ffma2(acc[2][2], wB.x, bz); ffma2(acc[2][3], wB.y, bz);
                ffma2(acc[3][0], wA.x, bw); ffma2(acc[3][1], wA.y, bw);
                ffma2(acc[3][2], wB.x, bw); ffma2(acc[3][3], wB.y, bw);
            }
            #pragma unroll
            for (int hh = 0; hh < 2; hh++) {
                float sg[4][4];
                float bxv[4][4];
                #pragma unroll
                for (int pp = 0; pp < 4; pp++) {
                    float lo, hi;
                    f2unpack(acc[pp][2*hh],   lo, hi);
                    sg[pp][0] = 1.f/(1.f + __expf(-lo));
                    sg[pp][1] = 1.f/(1.f + __expf(-hi));
                    f2unpack(acc[pp][2*hh+1], lo, hi);
                    sg[pp][2] = 1.f/(1.f + __expf(-lo));
                    sg[pp][3] = 1.f/(1.f + __expf(-hi));
                    int j = s_idx[p0 + pp];
                    float4 gv = *(const float4*)(g_bxT + ((size_t)b*NN + j)*64 + o0 + 4*hh);
                    bxv[pp][0] = gv.x; bxv[pp][1] = gv.y; bxv[pp][2] = gv.z; bxv[pp][3] = gv.w;
                }
                #pragma unroll
                for (int oo = 0; oo < 4; oo++) {
                    int row = o0 + 4*hh + oo;
                    float ab = wab[row];
                    float4 rv = *(float4*)&t_rif[row*128 + p0];
                    rv.x = fmaxf(rv.x * sg[0][oo] * bxv[0][oo] + ab, 0.f);
                    rv.y = fmaxf(rv.y * sg[1][oo] * bxv[1][oo] + ab, 0.f);
                    rv.z = fmaxf(rv.z * sg[2][oo] * bxv[2][oo] + ab, 0.f);
                    rv.w = fmaxf(rv.w * sg[3][oo] * bxv[3][oo] + ab, 0.f);
                    *(float4*)&t_rif[row*128 + p0] = rv;
                }
            }
        }
        __syncthreads();   // C

        // GEMM5: edge [64x128], K=64; running max
        {
            const int o0 = w*8;
            u64 acc[4][4];
            #pragma unroll
            for (int pp = 0; pp < 4; pp++)
                #pragma unroll
                for (int pr = 0; pr < 4; pr++) acc[pp][pr] = 0ull;
            #pragma unroll 4
            for (int c = 0; c < 64; c++) {
                ulonglong2 wA = *(const ulonglong2*)&wWEt[c*64 + o0];
                ulonglong2 wB = *(const ulonglong2*)&wWEt[c*64 + o0 + 4];
                float4 bv = *(float4*)&t_rif[c*128 + p0];
                u64 bx = f2pack(bv.x,bv.x), by = f2pack(bv.y,bv.y);
                u64 bz = f2pack(bv.z,bv.z), bw = f2pack(bv.w,bv.w);
                ffma2(acc[0][0], wA.x, bx); ffma2(acc[0][1], wA.y, bx);
                ffma2(acc[0][2], wB.x, bx); ffma2(acc[0][3], wB.y, bx);
                ffma2(acc[1][0], wA.x, by); ffma2(acc[1][1], wA.y, by);
                ffma2(acc[1][2], wB.x, by); ffma2(acc[1][3], wB.y, by);
                ffma2(acc[2][0], wA.x, bz); ffma2(acc[2][1], wA.y, bz);
                ffma2(acc[2][2], wB.x, bz); ffma2(acc[2][3], wB.y, bz);
                ffma2(acc[3][0], wA.x, bw); ffma2(acc[3][1], wA.y, bw);
                ffma2(acc[3][2], wB.x, bw); ffma2(acc[3][3], wB.y, bw);
            }
            #pragma unroll
            for (int pp = 0; pp < 4; pp++) {
                #pragma unroll
                for (int pr = 0; pr < 4; pr++) {
                    float lo, hi;
                    f2unpack(acc[pp][pr], lo, hi);
                    mx[pp][2*pr]   = fmaxf(mx[pp][2*pr],   lo);
                    mx[pp][2*pr+1] = fmaxf(mx[pp][2*pr+1], hi);
                }
            }
        }
        __syncthreads();   // D
    }

    // epilogue: out = leaky(mx + cst)
    {
        const int o0 = w*8;
        #pragma unroll
        for (int hh = 0; hh < 2; hh++) {
            float cc[4][4];
            #pragma unroll
            for (int pp = 0; pp < 4; pp++) {
                float4 cv = *(const float4*)(g_cst + ((size_t)b*NN + n0 + p0 + pp)*64 + o0 + 4*hh);
                cc[pp][0]=cv.x; cc[pp][1]=cv.y; cc[pp][2]=cv.z; cc[pp][3]=cv.w;
            }
            #pragma unroll
            for (int oo = 0; oo < 4; oo++) {
                int row = o0 + 4*hh + oo;
                float4 v;
                v.x = LEAKY(mx[0][4*hh+oo] + cc[0][oo]);
                v.y = LEAKY(mx[1][4*hh+oo] + cc[1][oo]);
                v.z = LEAKY(mx[2][4*hh+oo] + cc[2][oo]);
                v.w = LEAKY(mx[3][4*hh+oo] + cc[3][oo]);
                *(float4*)&out[((size_t)b*64 + row)*NN + n0 + p0] = v;
            }
        }
    }
}

// =====================================================================
extern "C" void kernel_launch(void* const* d_in, const int* in_sizes, int n_in,
                              void* d_out, int out_size)
{
    const float* pos     = (const float*)d_in[0];
    const float* x       = (const float*)d_in[1];
    const float* glf     = (const float*)d_in[2];
    const float* appf    = (const float*)d_in[3];
    const float* basis_W = (const float*)d_in[4];
    const float* dk_W1   = (const float*)d_in[5];
    const float* dk_b1   = (const float*)d_in[6];
    const float* dk_g1   = (const float*)d_in[7];
    const float* dk_be1  = (const float*)d_in[8];
    const float* dk_W2   = (const float*)d_in[9];
    const float* dk_b2   = (const float*)d_in[10];
    const float* act_g   = (const float*)d_in[11];
    const float* act_b   = (const float*)d_in[12];
    const float* ff_W1   = (const float*)d_in[13];
    const float* ff_g1   = (const float*)d_in[14];
    const float* ff_be1  = (const float*)d_in[15];
    const float* ff_W2   = (const float*)d_in[16];
    const float* edge_W  = (const float*)d_in[17];
    const float* edge_g  = (const float*)d_in[18];
    const float* edge_be = (const float*)d_in[19];
    float* out = (float*)d_out;

    // mega: knn (1024 blocks) + glf transpose (4096 blocks), tr hidden
    // under knn's runtime. smem = max(knn 32KB, tr 21KB).
    mega_kernel<<<5120, 256, 2048*16>>>(pos, glf);

    prep_kernel<<<(NB*NN)/128, 128>>>(x, basis_W, edge_W, act_g, edge_g, edge_be);

    const int smem_bytes = (128+16+512+32+512+32+1024+2048+64+4096 + 1024+2048+8192+4096 + 128) * (int)sizeof(float);
    cudaFuncSetAttribute(main_kernel, cudaFuncAttributeMaxDynamicSharedMemorySize, smem_bytes);
    main_kernel<<<NB*NN/128, 256, smem_bytes>>>(appf,
                                                dk_W1, dk_b1, dk_g1, dk_be1,
                                                dk_W2, dk_b2, act_b,
                                                ff_W1, ff_g1, ff_be1, ff_W2,
                                                edge_W, edge_g, out);
}